// round 4
// baseline (speedup 1.0000x reference)
#include <cuda_runtime.h>
#include <math.h>

#define Nn 8
#define Cc 256
#define Ll 512
#define Kk 100
#define ROWS (Nn * Ll)          // 4096
#define INV_TEMP 2.0f           // 1/0.5
#define EPS 1e-8f

// Scratch (no runtime allocation allowed)
__device__ float g_zn[ROWS * Cc];   // z transposed + normalized, fp32
__device__ float g_cn[ROWS * Cc];   // c transposed + normalized * INV_TEMP, fp32
__device__ float g_inv[2 * ROWS];   // [0..ROWS): invz, [ROWS..): invc*flavor

// ---------------------------------------------------------------------------
// Norms straight from the ORIGINAL (N, C, cols) layout — column reductions.
// Block = 256 threads = (c-split s = tid>>5 in 0..7) x (l-lane g = tid&31).
// Each block: one (tensor, n, 32-l tile). Thread sums 32 c's, coalesced in l.
// grid = 2 * 8 * 16 = 256 blocks.
// ---------------------------------------------------------------------------
__global__ void norms_k(const float* __restrict__ z, const float* __restrict__ c)
{
    __shared__ float part[8][33];

    int bb    = blockIdx.x;
    int which = bb >> 7;            // 0: z, 1: c
    int n     = (bb >> 4) & 7;
    int lt    = bb & 15;            // 16 l-tiles of 32
    int cols  = which ? (Ll + 1) : Ll;
    int off   = which ? 1 : 0;
    const float* src = (which ? c : z) + (size_t)n * Cc * cols + off + lt * 32;

    int g = threadIdx.x & 31;
    int s = threadIdx.x >> 5;

    float acc = 0.f;
#pragma unroll 8
    for (int cc = s * 32; cc < s * 32 + 32; cc++)
        { float v = src[(size_t)cc * cols + g]; acc += v * v; }
    part[s][g] = acc;
    __syncthreads();

    if (threadIdx.x < 32) {
        float t = 0.f;
#pragma unroll
        for (int k = 0; k < 8; k++) t += part[k][g];
        float inv = 1.0f / fmaxf(sqrtf(t), EPS);
        if (which) inv *= INV_TEMP;
        g_inv[which * ROWS + n * Ll + lt * 32 + g] = inv;
    }
}

// ---------------------------------------------------------------------------
// Fused transpose + normalize: (N, C, cols) -> (N*L, C) fp32, scaled per-row.
// blockIdx.z: 0..7 -> z, 8..15 -> c. grid (16, 8, 16), block (32, 8).
// ---------------------------------------------------------------------------
__global__ void tscale_k(const float* __restrict__ z, const float* __restrict__ c)
{
    __shared__ float tile[32][33];

    int which = blockIdx.z >> 3;
    int n     = blockIdx.z & 7;
    int cols  = which ? (Ll + 1) : Ll;
    int off   = which ? 1 : 0;
    const float* in = which ? c : z;
    float* out      = which ? g_cn : g_zn;

    int l0 = blockIdx.x * 32;
    int c0 = blockIdx.y * 32;
    int tx = threadIdx.x, ty = threadIdx.y;

    const float* src = in + (size_t)n * Cc * cols + off;
#pragma unroll
    for (int i = 0; i < 32; i += 8)
        tile[ty + i][tx] = src[(size_t)(c0 + ty + i) * cols + l0 + tx];
    __syncthreads();

    int rbase = n * Ll + l0;
#pragma unroll
    for (int i = 0; i < 32; i += 8) {
        int row = rbase + ty + i;
        float sc = g_inv[which * ROWS + row];
        out[(size_t)row * Cc + c0 + tx] = tile[tx][ty + i] * sc;
    }
}

// ---------------------------------------------------------------------------
// Main: one block per row, 128 threads = 8 half-warps. Half-warp h owns dots
// d = h + 8*it (13 iters; d==100 is the positive). Pre-normalized fp32 rows:
// the dot IS the logit. Loads arrive as 64-bit pairs -> fma.rn.f32x2 with
// zero unpack instructions. 4 shuffles per dot, amortized 2/dot per warp.
// ---------------------------------------------------------------------------
__global__ void logits_k(const int* __restrict__ neg_inds, float* __restrict__ out)
{
    __shared__ float2 c_sh[Cc / 2];
    __shared__ float logit_sh[Kk + 1];

    int row = blockIdx.x;
    int tid = threadIdx.x;
    int h   = tid >> 4;                       // half-warp id 0..7
    int hl  = tid & 15;                       // lane in half-warp
    unsigned hmask = 0xFFFFu << (tid & 16);   // this half-warp's lane mask

    c_sh[tid] = ((const float2*)(g_cn + (size_t)row * Cc))[tid];
    __syncthreads();

    // this lane's 8 packed c pairs (elements [16*hl, 16*hl+16))
    unsigned long long cp[8];
#pragma unroll
    for (int t = 0; t < 8; t++) {
        float2 f = c_sh[8 * hl + t];
        asm("mov.b64 %0, {%1, %2};" : "=l"(cp[t]) : "f"(f.x), "f"(f.y));
    }

    const int* inds = neg_inds + (size_t)row * Kk;

#pragma unroll 1
    for (int it = 0; it < 13; it++) {
        int d = h + it * 8;
        if (d <= Kk) {
            int j = (d == Kk) ? row : __ldg(&inds[d]);
            const ulonglong2* zr = (const ulonglong2*)(g_zn + (size_t)j * Cc) + 4 * hl;
            ulonglong2 q0 = zr[0];
            ulonglong2 q1 = zr[1];
            ulonglong2 q2 = zr[2];
            ulonglong2 q3 = zr[3];

            unsigned long long a0 = 0, a1 = 0, a2 = 0, a3 = 0;
            asm("fma.rn.f32x2 %0,%1,%2,%0;" : "+l"(a0) : "l"(q0.x), "l"(cp[0]));
            asm("fma.rn.f32x2 %0,%1,%2,%0;" : "+l"(a1) : "l"(q0.y), "l"(cp[1]));
            asm("fma.rn.f32x2 %0,%1,%2,%0;" : "+l"(a2) : "l"(q1.x), "l"(cp[2]));
            asm("fma.rn.f32x2 %0,%1,%2,%0;" : "+l"(a3) : "l"(q1.y), "l"(cp[3]));
            asm("fma.rn.f32x2 %0,%1,%2,%0;" : "+l"(a0) : "l"(q2.x), "l"(cp[4]));
            asm("fma.rn.f32x2 %0,%1,%2,%0;" : "+l"(a1) : "l"(q2.y), "l"(cp[5]));
            asm("fma.rn.f32x2 %0,%1,%2,%0;" : "+l"(a2) : "l"(q3.x), "l"(cp[6]));
            asm("fma.rn.f32x2 %0,%1,%2,%0;" : "+l"(a3) : "l"(q3.y), "l"(cp[7]));

            unsigned long long b0, b1, bs;
            asm("add.rn.f32x2 %0,%1,%2;" : "=l"(b0) : "l"(a0), "l"(a1));
            asm("add.rn.f32x2 %0,%1,%2;" : "=l"(b1) : "l"(a2), "l"(a3));
            asm("add.rn.f32x2 %0,%1,%2;" : "=l"(bs) : "l"(b0), "l"(b1));
            float lo, hi;
            asm("mov.b64 {%0,%1}, %2;" : "=f"(lo), "=f"(hi) : "l"(bs));
            float s = lo + hi;
#pragma unroll
            for (int off = 8; off; off >>= 1)
                s += __shfl_xor_sync(hmask, s, off);
            if (hl == 0)
                logit_sh[(d == Kk) ? 0 : d + 1] = s;
        }
    }
    __syncthreads();

    if (tid < 32) {
        int lane = tid;
        float v0 = logit_sh[lane];
        float v1 = (lane + 32 < Kk + 1) ? logit_sh[lane + 32] : -INFINITY;
        float v2 = (lane + 64 < Kk + 1) ? logit_sh[lane + 64] : -INFINITY;
        float v3 = (lane + 96 < Kk + 1) ? logit_sh[lane + 96] : -INFINITY;
        float m = fmaxf(fmaxf(v0, v1), fmaxf(v2, v3));
#pragma unroll
        for (int off = 16; off; off >>= 1)
            m = fmaxf(m, __shfl_xor_sync(0xffffffffu, m, off));
        float e = __expf(v0 - m)
                + ((lane + 32 < Kk + 1) ? __expf(v1 - m) : 0.0f)
                + ((lane + 64 < Kk + 1) ? __expf(v2 - m) : 0.0f)
                + ((lane + 96 < Kk + 1) ? __expf(v3 - m) : 0.0f);
#pragma unroll
        for (int off = 16; off; off >>= 1)
            e += __shfl_xor_sync(0xffffffffu, e, off);
        if (lane == 0) {
            float item = m + logf(e) - logit_sh[0];
            atomicAdd(out, item * (1.0f / (float)ROWS));
        }
    }
}

extern "C" void kernel_launch(void* const* d_in, const int* in_sizes, int n_in,
                              void* d_out, int out_size)
{
    const float* z  = (const float*)d_in[0];   // (8, 256, 512)
    const float* c  = (const float*)d_in[1];   // (8, 256, 513)
    const int* inds = (const int*)d_in[2];     // (8, 512, 100)
    float* out = (float*)d_out;

    norms_k<<<256, 256>>>(z, c);

    dim3 tb(32, 8);
    dim3 tg(Ll / 32, Cc / 32, 2 * Nn);         // (16, 8, 16)
    tscale_k<<<tg, tb>>>(z, c);

    cudaMemsetAsync(d_out, 0, sizeof(float));
    logits_k<<<ROWS, 128>>>(inds, out);
}

// round 5
// speedup vs baseline: 2.4836x; 2.4836x over previous
#include <cuda_runtime.h>
#include <cuda_fp16.h>
#include <math.h>

#define Nn 8
#define Cc 256
#define Ll 512
#define Kk 100
#define ROWS (Nn * Ll)          // 4096
#define INV_TEMP 2.0f           // 1/0.5
#define EPS 1e-8f

// Scratch (no runtime allocation allowed)
__device__ __half g_zh[ROWS * Cc];    // z transposed + normalized, fp16 (2MB, L2-resident)
__device__ __half g_ch[ROWS * Cc];    // c transposed + normalized * INV_TEMP, fp16
__device__ float g_part[2 * ROWS * 4];// per-(tensor,row) quarter sum-of-squares

// ---------------------------------------------------------------------------
// Norms from the ORIGINAL (N, C, cols) layout. grid=1024:
// [which(2)][n(8)][ltile(16)][cquarter(4)], block=256 = 8 c-subgroups x 32 l.
// Thread sums 8 c's (MLP=8, coalesced in l). Also zeroes out[0] (block 0).
// ---------------------------------------------------------------------------
__global__ void norms_k(const float* __restrict__ z, const float* __restrict__ c,
                        float* __restrict__ out)
{
    __shared__ float part[8][33];

    int bb    = blockIdx.x;
    int cq    = bb & 3;
    int lt    = (bb >> 2) & 15;
    int n     = (bb >> 6) & 7;
    int which = bb >> 9;

    if (bb == 0 && threadIdx.x == 0) out[0] = 0.0f;

    int cols = which ? (Ll + 1) : Ll;
    const float* src = (which ? c : z) + (size_t)n * Cc * cols + (which ? 1 : 0)
                     + lt * 32;

    int g  = threadIdx.x & 31;
    int s  = threadIdx.x >> 5;
    int c0 = cq * 64 + s * 8;

    float acc = 0.f;
#pragma unroll
    for (int i = 0; i < 8; i++) {
        float v = src[(size_t)(c0 + i) * cols + g];
        acc += v * v;
    }
    part[s][g] = acc;
    __syncthreads();

    if (threadIdx.x < 32) {
        float t = 0.f;
#pragma unroll
        for (int k = 0; k < 8; k++) t += part[k][g];
        int row = n * Ll + lt * 32 + g;
        g_part[(which * ROWS + row) * 4 + cq] = t;
    }
}

// ---------------------------------------------------------------------------
// Fused transpose + normalize + fp16 convert: (N, C, cols) -> (N*L, C) fp16.
// blockIdx.z: 0..7 -> z, 8..15 -> c (c gets INV_TEMP folded in).
// grid (16, 8, 16), block (32, 8).
// ---------------------------------------------------------------------------
__global__ void tscale_k(const float* __restrict__ z, const float* __restrict__ c)
{
    __shared__ float tile[32][33];
    __shared__ float inv_sh[32];

    int which = blockIdx.z >> 3;
    int n     = blockIdx.z & 7;
    int cols  = which ? (Ll + 1) : Ll;
    const float* in = which ? c : z;
    __half* out     = which ? g_ch : g_zh;

    int l0 = blockIdx.x * 32;
    int c0 = blockIdx.y * 32;
    int tx = threadIdx.x, ty = threadIdx.y;

    const float* src = in + (size_t)n * Cc * cols + (which ? 1 : 0);
#pragma unroll
    for (int i = 0; i < 32; i += 8)
        tile[ty + i][tx] = src[(size_t)(c0 + ty + i) * cols + l0 + tx];

    if (ty == 0) {
        int row = n * Ll + l0 + tx;
        const float* p = g_part + (size_t)(which * ROWS + row) * 4;
        float ssum = p[0] + p[1] + p[2] + p[3];
        float iv = 1.0f / fmaxf(sqrtf(ssum), EPS);
        if (which) iv *= INV_TEMP;
        inv_sh[tx] = iv;
    }
    __syncthreads();

    int rbase = n * Ll + l0;
#pragma unroll
    for (int i = 0; i < 32; i += 8)
        out[(size_t)(rbase + ty + i) * Cc + c0 + tx] =
            __float2half_rn(tile[tx][ty + i] * inv_sh[ty + i]);
}

// ---------------------------------------------------------------------------
// Main: one block per row, 128 threads = 8 half-warps. Half-warp h owns dots
// d = h + 8*it (13 iters; d==100 is the positive). Rows pre-normalized fp16:
// the dot IS the logit. Per lane: 2 coalesced LDG.128 (256B contiguous per
// half-warp per instruction) + 8 HFMA2 (two 4-deep half2 accumulators) +
// 2 f32 converts + 4 shuffles.
// ---------------------------------------------------------------------------
__global__ void logits_k(const int* __restrict__ neg_inds, float* __restrict__ out)
{
    __shared__ uint4 c_sh[32];          // 512B: this row's c in fp16
    __shared__ float logit_sh[Kk + 1];

    int row = blockIdx.x;
    int tid = threadIdx.x;
    int h   = tid >> 4;                       // half-warp id 0..7
    int hl  = tid & 15;                       // lane in half-warp
    unsigned hmask = 0xFFFFu << (tid & 16);

    if (tid < 32)
        c_sh[tid] = ((const uint4*)(g_ch + (size_t)row * Cc))[tid];
    __syncthreads();

    // lane's 16 c elements: [8*hl, 8*hl+8) and [128+8*hl, 128+8*hl+8)
    uint4 ca = c_sh[hl];
    uint4 cb = c_sh[16 + hl];
    __half2 cc0 = *(__half2*)&ca.x, cc1 = *(__half2*)&ca.y;
    __half2 cc2 = *(__half2*)&ca.z, cc3 = *(__half2*)&ca.w;
    __half2 cc4 = *(__half2*)&cb.x, cc5 = *(__half2*)&cb.y;
    __half2 cc6 = *(__half2*)&cb.z, cc7 = *(__half2*)&cb.w;

    const int* inds = neg_inds + (size_t)row * Kk;

#pragma unroll 1
    for (int it = 0; it < 13; it++) {
        int d = h + it * 8;
        if (d <= Kk) {
            int j = (d == Kk) ? row : __ldg(&inds[d]);
            const uint4* zr = (const uint4*)(g_zh + (size_t)j * Cc);
            uint4 za = zr[hl];          // bytes [16*hl, 16*hl+16)
            uint4 zb = zr[16 + hl];     // bytes [256+16*hl, ...)

            __half2 a0 = __float2half2_rn(0.f);
            __half2 a1 = __float2half2_rn(0.f);
            a0 = __hfma2(*(__half2*)&za.x, cc0, a0);
            a0 = __hfma2(*(__half2*)&za.y, cc1, a0);
            a0 = __hfma2(*(__half2*)&za.z, cc2, a0);
            a0 = __hfma2(*(__half2*)&za.w, cc3, a0);
            a1 = __hfma2(*(__half2*)&zb.x, cc4, a1);
            a1 = __hfma2(*(__half2*)&zb.y, cc5, a1);
            a1 = __hfma2(*(__half2*)&zb.z, cc6, a1);
            a1 = __hfma2(*(__half2*)&zb.w, cc7, a1);

            float2 f0 = __half22float2(a0);
            float2 f1 = __half22float2(a1);
            float s = (f0.x + f0.y) + (f1.x + f1.y);
#pragma unroll
            for (int off = 8; off; off >>= 1)
                s += __shfl_xor_sync(hmask, s, off);
            if (hl == 0)
                logit_sh[(d == Kk) ? 0 : d + 1] = s;
        }
    }
    __syncthreads();

    if (tid < 32) {
        int lane = tid;
        float v0 = logit_sh[lane];
        float v1 = (lane + 32 < Kk + 1) ? logit_sh[lane + 32] : -INFINITY;
        float v2 = (lane + 64 < Kk + 1) ? logit_sh[lane + 64] : -INFINITY;
        float v3 = (lane + 96 < Kk + 1) ? logit_sh[lane + 96] : -INFINITY;
        float m = fmaxf(fmaxf(v0, v1), fmaxf(v2, v3));
#pragma unroll
        for (int off = 16; off; off >>= 1)
            m = fmaxf(m, __shfl_xor_sync(0xffffffffu, m, off));
        float e = __expf(v0 - m)
                + ((lane + 32 < Kk + 1) ? __expf(v1 - m) : 0.0f)
                + ((lane + 64 < Kk + 1) ? __expf(v2 - m) : 0.0f)
                + ((lane + 96 < Kk + 1) ? __expf(v3 - m) : 0.0f);
#pragma unroll
        for (int off = 16; off; off >>= 1)
            e += __shfl_xor_sync(0xffffffffu, e, off);
        if (lane == 0) {
            float item = m + logf(e) - logit_sh[0];
            atomicAdd(out, item * (1.0f / (float)ROWS));
        }
    }
}

extern "C" void kernel_launch(void* const* d_in, const int* in_sizes, int n_in,
                              void* d_out, int out_size)
{
    const float* z  = (const float*)d_in[0];   // (8, 256, 512)
    const float* c  = (const float*)d_in[1];   // (8, 256, 513)
    const int* inds = (const int*)d_in[2];     // (8, 512, 100)
    float* out = (float*)d_out;

    norms_k<<<1024, 256>>>(z, c, out);

    dim3 tb(32, 8);
    dim3 tg(Ll / 32, Cc / 32, 2 * Nn);         // (16, 8, 16)
    tscale_k<<<tg, tb>>>(z, c);

    logits_k<<<ROWS, 128>>>(inds, out);
}